// round 7
// baseline (speedup 1.0000x reference)
#include <cuda_runtime.h>
#include <math.h>

#define BATCH 4
#define SEQ   2048
#define DMODEL 1024
#define NHEAD 16
#define HDIM  64

#define GM (BATCH*SEQ)   // 8192
#define GN DMODEL        // 1024
#define GK DMODEL        // 1024

// Scratch: q,k,v in [B,H,S,HD]; attn output in [B,S,D]
__device__ float g_q[BATCH*NHEAD*SEQ*HDIM];
__device__ float g_k[BATCH*NHEAD*SEQ*HDIM];
__device__ float g_v[BATCH*NHEAD*SEQ*HDIM];
__device__ float g_att[BATCH*SEQ*DMODEL];

// ---------------------------------------------------------------------------
// Fused QKV GEMM: one launch, gridDim.z = 3 selects (Wq,bq,q)/(Wk,bk,k)/(Wv,bv,v).
// C[m,n] = sum_k X[m,k]*W[n,k] + bias, stored permuted into [B,H,S,HD].
// 128x128 tile, BK=8, 256 threads, 8x8 per thread, k-major smem (transposed
// on store, padded) so the inner loop is 4x LDS.128 per 64 FMA.
// ---------------------------------------------------------------------------
__global__ __launch_bounds__(256) void gemm_qkv(
    const float* __restrict__ X,
    const float* __restrict__ Wq, const float* __restrict__ bq, float* __restrict__ oq,
    const float* __restrict__ Wk, const float* __restrict__ bk, float* __restrict__ ok,
    const float* __restrict__ Wv, const float* __restrict__ bv, float* __restrict__ ov)
{
    const float* W; const float* b1; float* out;
    if (blockIdx.z == 0)      { W = Wq; b1 = bq; out = oq; }
    else if (blockIdx.z == 1) { W = Wk; b1 = bk; out = ok; }
    else                      { W = Wv; b1 = bv; out = ov; }

    __shared__ float As[8][132];   // [k][m], padded
    __shared__ float Bs[8][132];   // [k][n], padded

    const int n0 = blockIdx.x * 128;
    const int m0 = blockIdx.y * 128;
    const int tid = threadIdx.x;
    const int ty = tid >> 4;        // 0..15
    const int tx = tid & 15;        // 0..15
    const int lr = tid >> 1;        // 0..127 (load row)
    const int lc = (tid & 1) * 4;   // 0 or 4 (load col base)

    float acc[8][8];
#pragma unroll
    for (int i = 0; i < 8; ++i)
#pragma unroll
        for (int j = 0; j < 8; ++j) acc[i][j] = 0.0f;

    const float* Xp = X + (size_t)(m0 + lr) * GK + lc;
    const float* Wp = W + (size_t)(n0 + lr) * GK + lc;

    for (int kt = 0; kt < GK; kt += 8) {
        const float4 a4 = *(const float4*)(Xp + kt);
        const float4 b4 = *(const float4*)(Wp + kt);
        __syncthreads();   // previous iteration's compute done before overwrite
        As[lc + 0][lr] = a4.x; As[lc + 1][lr] = a4.y;
        As[lc + 2][lr] = a4.z; As[lc + 3][lr] = a4.w;
        Bs[lc + 0][lr] = b4.x; Bs[lc + 1][lr] = b4.y;
        Bs[lc + 2][lr] = b4.z; Bs[lc + 3][lr] = b4.w;
        __syncthreads();
#pragma unroll
        for (int k = 0; k < 8; ++k) {
            float a[8], b[8];
            *(float4*)&a[0] = *(const float4*)&As[k][ty * 8];
            *(float4*)&a[4] = *(const float4*)&As[k][ty * 8 + 4];
            *(float4*)&b[0] = *(const float4*)&Bs[k][tx * 8];
            *(float4*)&b[4] = *(const float4*)&Bs[k][tx * 8 + 4];
#pragma unroll
            for (int i = 0; i < 8; ++i)
#pragma unroll
                for (int j = 0; j < 8; ++j)
                    acc[i][j] = fmaf(a[i], b[j], acc[i][j]);
        }
    }

#pragma unroll
    for (int i = 0; i < 8; ++i) {
        const int m = m0 + ty * 8 + i;
        const int bb = m >> 11;        // /SEQ
        const int ss = m & (SEQ - 1);
#pragma unroll
        for (int j = 0; j < 8; ++j) {
            const int n = n0 + tx * 8 + j;
            const int h  = n >> 6;         // /HDIM
            const int d  = n & (HDIM - 1);
            out[(((size_t)bb * NHEAD + h) * SEQ + ss) * HDIM + d] = acc[i][j] + b1[n];
        }
    }
}

// ---------------------------------------------------------------------------
// Output projection GEMM: row-major [M,N] out, adds bias + comp.
// Same tiling as gemm_qkv.
// ---------------------------------------------------------------------------
__global__ __launch_bounds__(256) void gemm_out(
    const float* __restrict__ X, const float* __restrict__ W,
    const float* __restrict__ b1, const float* __restrict__ b2,
    float* __restrict__ out)
{
    __shared__ float As[8][132];
    __shared__ float Bs[8][132];

    const int n0 = blockIdx.x * 128;
    const int m0 = blockIdx.y * 128;
    const int tid = threadIdx.x;
    const int ty = tid >> 4;
    const int tx = tid & 15;
    const int lr = tid >> 1;
    const int lc = (tid & 1) * 4;

    float acc[8][8];
#pragma unroll
    for (int i = 0; i < 8; ++i)
#pragma unroll
        for (int j = 0; j < 8; ++j) acc[i][j] = 0.0f;

    const float* Xp = X + (size_t)(m0 + lr) * GK + lc;
    const float* Wp = W + (size_t)(n0 + lr) * GK + lc;

    for (int kt = 0; kt < GK; kt += 8) {
        const float4 a4 = *(const float4*)(Xp + kt);
        const float4 b4 = *(const float4*)(Wp + kt);
        __syncthreads();
        As[lc + 0][lr] = a4.x; As[lc + 1][lr] = a4.y;
        As[lc + 2][lr] = a4.z; As[lc + 3][lr] = a4.w;
        Bs[lc + 0][lr] = b4.x; Bs[lc + 1][lr] = b4.y;
        Bs[lc + 2][lr] = b4.z; Bs[lc + 3][lr] = b4.w;
        __syncthreads();
#pragma unroll
        for (int k = 0; k < 8; ++k) {
            float a[8], b[8];
            *(float4*)&a[0] = *(const float4*)&As[k][ty * 8];
            *(float4*)&a[4] = *(const float4*)&As[k][ty * 8 + 4];
            *(float4*)&b[0] = *(const float4*)&Bs[k][tx * 8];
            *(float4*)&b[4] = *(const float4*)&Bs[k][tx * 8 + 4];
#pragma unroll
            for (int i = 0; i < 8; ++i)
#pragma unroll
                for (int j = 0; j < 8; ++j)
                    acc[i][j] = fmaf(a[i], b[j], acc[i][j]);
        }
    }

#pragma unroll
    for (int i = 0; i < 8; ++i) {
        const int m = m0 + ty * 8 + i;
#pragma unroll
        for (int j = 0; j < 8; ++j) {
            const int n = n0 + tx * 8 + j;
            out[(size_t)m * GN + n] = acc[i][j] + b1[n] + b2[n];
        }
    }
}

// ---------------------------------------------------------------------------
// Flash attention, fp32, causal. One CTA = (bh, 64-row q-tile).
// 256 threads, 4x4 micro-tiles over a 64x64 score tile; 16-lane shfl
// reductions for row max/sum. Dynamic shared: Qs(64x64) Ks(64x65) Vs(64x64)
// Ps(64x64).
// ---------------------------------------------------------------------------
__global__ __launch_bounds__(256) void attn_kernel(
    const float* __restrict__ Q, const float* __restrict__ K,
    const float* __restrict__ V, float* __restrict__ O)
{
    extern __shared__ float sm[];
    float* Qs = sm;                 // 64*64
    float* Ks = Qs + 64 * 64;       // 64*65 (padded)
    float* Vs = Ks + 64 * 65;       // 64*64
    float* Ps = Vs + 64 * 64;       // 64*64

    const int qt = blockIdx.x;
    const int bh = blockIdx.y;
    const int q0 = qt * 64;
    const int tid = threadIdx.x;
    const int ty = tid >> 4;
    const int tx = tid & 15;

    const float* Qb = Q + (size_t)bh * SEQ * HDIM;
    const float* Kb = K + (size_t)bh * SEQ * HDIM;
    const float* Vb = V + (size_t)bh * SEQ * HDIM;

    // Load Q tile, pre-scaled by 1/sqrt(HD)=0.125
#pragma unroll
    for (int it = 0; it < 4; ++it) {
        int lin = it * 1024 + tid * 4;
        int r = lin >> 6, c = lin & 63;
        float4 v4 = *(const float4*)&Qb[(size_t)(q0 + r) * HDIM + c];
        v4.x *= 0.125f; v4.y *= 0.125f; v4.z *= 0.125f; v4.w *= 0.125f;
        *(float4*)&Qs[r * 64 + c] = v4;
    }

    float m_i[4], l_i[4], o[4][4];
#pragma unroll
    for (int i = 0; i < 4; ++i) {
        m_i[i] = -INFINITY; l_i[i] = 0.0f;
#pragma unroll
        for (int j = 0; j < 4; ++j) o[i][j] = 0.0f;
    }
    __syncthreads();

    const int ntiles = qt + 1;  // causal
    for (int t = 0; t < ntiles; ++t) {
        const int k0 = t * 64;
        // Load K (padded) and V tiles
#pragma unroll
        for (int it = 0; it < 4; ++it) {
            int lin = it * 1024 + tid * 4;
            int r = lin >> 6, c = lin & 63;
            float4 kv = *(const float4*)&Kb[(size_t)(k0 + r) * HDIM + c];
            Ks[r * 65 + c + 0] = kv.x; Ks[r * 65 + c + 1] = kv.y;
            Ks[r * 65 + c + 2] = kv.z; Ks[r * 65 + c + 3] = kv.w;
            float4 vv = *(const float4*)&Vb[(size_t)(k0 + r) * HDIM + c];
            *(float4*)&Vs[r * 64 + c] = vv;
        }
        __syncthreads();

        // S = Q' K^T
        float s[4][4];
#pragma unroll
        for (int i = 0; i < 4; ++i)
#pragma unroll
            for (int j = 0; j < 4; ++j) s[i][j] = 0.0f;
#pragma unroll 16
        for (int d = 0; d < 64; ++d) {
            float a[4], b[4];
#pragma unroll
            for (int i = 0; i < 4; ++i) a[i] = Qs[(ty * 4 + i) * 64 + d];
#pragma unroll
            for (int j = 0; j < 4; ++j) b[j] = Ks[(tx * 4 + j) * 65 + d];
#pragma unroll
            for (int i = 0; i < 4; ++i)
#pragma unroll
                for (int j = 0; j < 4; ++j)
                    s[i][j] = fmaf(a[i], b[j], s[i][j]);
        }

        if (t == qt) {  // diagonal tile: causal mask
#pragma unroll
            for (int i = 0; i < 4; ++i) {
                const int q = q0 + ty * 4 + i;
#pragma unroll
                for (int j = 0; j < 4; ++j)
                    if (k0 + tx * 4 + j > q) s[i][j] = -1e30f;
            }
        }

        // Online softmax
        float p[4][4];
#pragma unroll
        for (int i = 0; i < 4; ++i) {
            float rm = s[i][0];
#pragma unroll
            for (int j = 1; j < 4; ++j) rm = fmaxf(rm, s[i][j]);
#pragma unroll
            for (int off = 1; off < 16; off <<= 1)
                rm = fmaxf(rm, __shfl_xor_sync(0xFFFFFFFFu, rm, off));
            const float mnew = fmaxf(m_i[i], rm);
            float rs = 0.0f;
#pragma unroll
            for (int j = 0; j < 4; ++j) {
                p[i][j] = __expf(s[i][j] - mnew);
                rs += p[i][j];
            }
#pragma unroll
            for (int off = 1; off < 16; off <<= 1)
                rs += __shfl_xor_sync(0xFFFFFFFFu, rs, off);
            const float corr = __expf(m_i[i] - mnew);
            l_i[i] = l_i[i] * corr + rs;
            m_i[i] = mnew;
#pragma unroll
            for (int j = 0; j < 4; ++j) o[i][j] *= corr;
        }

        // Stage P to shared for the PV GEMM
#pragma unroll
        for (int i = 0; i < 4; ++i)
#pragma unroll
            for (int j = 0; j < 4; ++j)
                Ps[(ty * 4 + i) * 64 + tx * 4 + j] = p[i][j];
        __syncthreads();

        // O += P V  (Vs row reads are contiguous & 16B-aligned -> float4)
#pragma unroll 16
        for (int kk = 0; kk < 64; ++kk) {
            float a[4];
            float4 b4 = *(const float4*)&Vs[kk * 64 + tx * 4];
            const float b[4] = { b4.x, b4.y, b4.z, b4.w };
#pragma unroll
            for (int i = 0; i < 4; ++i) a[i] = Ps[(ty * 4 + i) * 64 + kk];
#pragma unroll
            for (int i = 0; i < 4; ++i)
#pragma unroll
                for (int j = 0; j < 4; ++j)
                    o[i][j] = fmaf(a[i], b[j], o[i][j]);
        }
        __syncthreads();
    }

    // Epilogue: normalize and write attn output as [B,S,D]
    const int bb = bh / NHEAD;
    const int h  = bh % NHEAD;
#pragma unroll
    for (int i = 0; i < 4; ++i) {
        const float inv = 1.0f / l_i[i];
        const int q = q0 + ty * 4 + i;
        float* row = O + ((size_t)bb * SEQ + q) * DMODEL + h * HDIM;
#pragma unroll
        for (int j = 0; j < 4; ++j)
            row[tx * 4 + j] = o[i][j] * inv;
    }
}

// ---------------------------------------------------------------------------

extern "C" void kernel_launch(void* const* d_in, const int* in_sizes, int n_in,
                              void* d_out, int out_size)
{
    (void)in_sizes; (void)n_in; (void)out_size;
    const float* x    = (const float*)d_in[0];
    const float* Wq   = (const float*)d_in[1];
    const float* bq   = (const float*)d_in[2];
    const float* Wk   = (const float*)d_in[3];
    const float* bk   = (const float*)d_in[4];
    const float* Wv   = (const float*)d_in[5];
    const float* bv   = (const float*)d_in[6];
    const float* Wo   = (const float*)d_in[7];
    const float* bo   = (const float*)d_in[8];
    const float* comp = (const float*)d_in[9];
    float* out = (float*)d_out;

    float *q, *k, *v, *att;
    cudaGetSymbolAddress((void**)&q,   g_q);
    cudaGetSymbolAddress((void**)&k,   g_k);
    cudaGetSymbolAddress((void**)&v,   g_v);
    cudaGetSymbolAddress((void**)&att, g_att);

    // Fused QKV: one launch, z selects projection. 1536 CTAs fill the chip.
    gemm_qkv<<<dim3(GN / 128, GM / 128, 3), 256>>>(
        x, Wq, bq, q, Wk, bk, k, Wv, bv, v);

    const int smem_bytes = (64 * 64 * 3 + 64 * 65) * (int)sizeof(float); // 65792
    cudaFuncSetAttribute(attn_kernel,
                         cudaFuncAttributeMaxDynamicSharedMemorySize, smem_bytes);
    attn_kernel<<<dim3(SEQ / 64, BATCH * NHEAD), 256, smem_bytes>>>(q, k, v, att);

    gemm_out<<<dim3(GN / 128, GM / 128), 256>>>(att, Wo, bo, comp, out);
}

// round 15
// speedup vs baseline: 1.1032x; 1.1032x over previous
#include <cuda_runtime.h>
#include <math.h>

#define BATCH 4
#define SEQ   2048
#define DMODEL 1024
#define NHEAD 16
#define HDIM  64

#define GM (BATCH*SEQ)   // 8192
#define GN DMODEL        // 1024
#define GK DMODEL        // 1024

// Scratch: q,k,v in [B,H,S,HD]; attn output in [B,S,D]
__device__ float g_q[BATCH*NHEAD*SEQ*HDIM];
__device__ float g_k[BATCH*NHEAD*SEQ*HDIM];
__device__ float g_v[BATCH*NHEAD*SEQ*HDIM];
__device__ float g_att[BATCH*SEQ*DMODEL];

// ---------------------------------------------------------------------------
// Double-buffered GEMM mainloop shared by both kernels.
// C[m,n] = sum_k X[m,k]*W[n,k]; 128x128 tile, BK=8, 256 threads, 8x8/thread.
// Smem k-major (transposed on store, padded): inner loop 4x LDS.128 / 64 FMA.
// 2-stage pipeline: prefetch next slab to regs during compute, 1 bar/iter.
// ---------------------------------------------------------------------------
__device__ __forceinline__ void gemm_mainloop(
    const float* __restrict__ Xp, const float* __restrict__ Wp,
    float (*As)[8][132], float (*Bs)[8][132],
    int ty, int tx, int lr, int lc, float acc[8][8])
{
    // Preload slab 0 into buffer 0
    {
        const float4 a4 = *(const float4*)(Xp);
        const float4 b4 = *(const float4*)(Wp);
        As[0][lc + 0][lr] = a4.x; As[0][lc + 1][lr] = a4.y;
        As[0][lc + 2][lr] = a4.z; As[0][lc + 3][lr] = a4.w;
        Bs[0][lc + 0][lr] = b4.x; Bs[0][lc + 1][lr] = b4.y;
        Bs[0][lc + 2][lr] = b4.z; Bs[0][lc + 3][lr] = b4.w;
    }
    __syncthreads();

    int s = 0;
    for (int kt = 0; kt < GK; kt += 8) {
        // Prefetch next slab (overlaps with compute below)
        float4 na, nb;
        const bool has_next = (kt + 8 < GK);
        if (has_next) {
            na = *(const float4*)(Xp + kt + 8);
            nb = *(const float4*)(Wp + kt + 8);
        }

        // Compute on buffer s
#pragma unroll
        for (int k = 0; k < 8; ++k) {
            float a[8], b[8];
            *(float4*)&a[0] = *(const float4*)&As[s][k][ty * 8];
            *(float4*)&a[4] = *(const float4*)&As[s][k][ty * 8 + 4];
            *(float4*)&b[0] = *(const float4*)&Bs[s][k][tx * 8];
            *(float4*)&b[4] = *(const float4*)&Bs[s][k][tx * 8 + 4];
#pragma unroll
            for (int i = 0; i < 8; ++i)
#pragma unroll
                for (int j = 0; j < 8; ++j)
                    acc[i][j] = fmaf(a[i], b[j], acc[i][j]);
        }

        // Stage next slab into the alternate buffer (safe: its last readers
        // finished before the barrier that ended the previous iteration)
        if (has_next) {
            const int ns = s ^ 1;
            As[ns][lc + 0][lr] = na.x; As[ns][lc + 1][lr] = na.y;
            As[ns][lc + 2][lr] = na.z; As[ns][lc + 3][lr] = na.w;
            Bs[ns][lc + 0][lr] = nb.x; Bs[ns][lc + 1][lr] = nb.y;
            Bs[ns][lc + 2][lr] = nb.z; Bs[ns][lc + 3][lr] = nb.w;
        }
        __syncthreads();
        s ^= 1;
    }
}

// ---------------------------------------------------------------------------
// Fused QKV GEMM: one launch, gridDim.z = 3 selects (Wq,bq,q)/(Wk,bk,k)/(Wv,bv,v).
// Stores permuted into [B,H,S,HD].
// ---------------------------------------------------------------------------
__global__ __launch_bounds__(256) void gemm_qkv(
    const float* __restrict__ X,
    const float* __restrict__ Wq, const float* __restrict__ bq, float* __restrict__ oq,
    const float* __restrict__ Wk, const float* __restrict__ bk, float* __restrict__ ok,
    const float* __restrict__ Wv, const float* __restrict__ bv, float* __restrict__ ov)
{
    const float* W; const float* b1; float* out;
    if (blockIdx.z == 0)      { W = Wq; b1 = bq; out = oq; }
    else if (blockIdx.z == 1) { W = Wk; b1 = bk; out = ok; }
    else                      { W = Wv; b1 = bv; out = ov; }

    __shared__ float As[2][8][132];
    __shared__ float Bs[2][8][132];

    const int n0 = blockIdx.x * 128;
    const int m0 = blockIdx.y * 128;
    const int tid = threadIdx.x;
    const int ty = tid >> 4;
    const int tx = tid & 15;
    const int lr = tid >> 1;
    const int lc = (tid & 1) * 4;

    float acc[8][8];
#pragma unroll
    for (int i = 0; i < 8; ++i)
#pragma unroll
        for (int j = 0; j < 8; ++j) acc[i][j] = 0.0f;

    gemm_mainloop(X + (size_t)(m0 + lr) * GK + lc,
                  W + (size_t)(n0 + lr) * GK + lc,
                  As, Bs, ty, tx, lr, lc, acc);

#pragma unroll
    for (int i = 0; i < 8; ++i) {
        const int m = m0 + ty * 8 + i;
        const int bb = m >> 11;        // /SEQ
        const int ss = m & (SEQ - 1);
#pragma unroll
        for (int j = 0; j < 8; ++j) {
            const int n = n0 + tx * 8 + j;
            const int h  = n >> 6;         // /HDIM
            const int d  = n & (HDIM - 1);
            out[(((size_t)bb * NHEAD + h) * SEQ + ss) * HDIM + d] = acc[i][j] + b1[n];
        }
    }
}

// ---------------------------------------------------------------------------
// Output projection GEMM: row-major [M,N] out, adds bias + comp.
// ---------------------------------------------------------------------------
__global__ __launch_bounds__(256) void gemm_out(
    const float* __restrict__ X, const float* __restrict__ W,
    const float* __restrict__ b1, const float* __restrict__ b2,
    float* __restrict__ out)
{
    __shared__ float As[2][8][132];
    __shared__ float Bs[2][8][132];

    const int n0 = blockIdx.x * 128;
    const int m0 = blockIdx.y * 128;
    const int tid = threadIdx.x;
    const int ty = tid >> 4;
    const int tx = tid & 15;
    const int lr = tid >> 1;
    const int lc = (tid & 1) * 4;

    float acc[8][8];
#pragma unroll
    for (int i = 0; i < 8; ++i)
#pragma unroll
        for (int j = 0; j < 8; ++j) acc[i][j] = 0.0f;

    gemm_mainloop(X + (size_t)(m0 + lr) * GK + lc,
                  W + (size_t)(n0 + lr) * GK + lc,
                  As, Bs, ty, tx, lr, lc, acc);

#pragma unroll
    for (int i = 0; i < 8; ++i) {
        const int m = m0 + ty * 8 + i;
#pragma unroll
        for (int j = 0; j < 8; ++j) {
            const int n = n0 + tx * 8 + j;
            out[(size_t)m * GN + n] = acc[i][j] + b1[n] + b2[n];
        }
    }
}

// ---------------------------------------------------------------------------
// Flash attention, fp32, causal. One CTA = (bh, 64-row q-tile).
// Q and K tiles stored d-major (QsT[d][row], KsT[d][col], pad 68) so the
// QK^T inner loop is 2x LDS.128 per 16 FMA instead of 8 scalar LDS.
// LPT scheduling: qt reversed vs blockIdx.x so longest (most K-tiles) CTAs
// launch first, packing the causal-imbalance tail with short CTAs.
// Dynamic shared: QsT(64x68) KsT(64x68) Vs(64x64) Ps(64x64) = 67584 B.
// ---------------------------------------------------------------------------
#define TPAD 68

__global__ __launch_bounds__(256) void attn_kernel(
    const float* __restrict__ Q, const float* __restrict__ K,
    const float* __restrict__ V, float* __restrict__ O)
{
    extern __shared__ float sm[];
    float* QsT = sm;                  // 64*68, QsT[d][r]
    float* KsT = QsT + 64 * TPAD;     // 64*68, KsT[d][c]
    float* Vs  = KsT + 64 * TPAD;     // 64*64, Vs[r][d]
    float* Ps  = Vs + 64 * 64;        // 64*64

    const int qt = gridDim.x - 1 - blockIdx.x;  // longest-first (LPT)
    const int bh = blockIdx.y;
    const int q0 = qt * 64;
    const int tid = threadIdx.x;
    const int ty = tid >> 4;
    const int tx = tid & 15;

    const float* Qb = Q + (size_t)bh * SEQ * HDIM;
    const float* Kb = K + (size_t)bh * SEQ * HDIM;
    const float* Vb = V + (size_t)bh * SEQ * HDIM;

    // Load Q tile transposed, pre-scaled by 1/sqrt(HD)=0.125
#pragma unroll
    for (int it = 0; it < 4; ++it) {
        int lin = it * 1024 + tid * 4;
        int r = lin >> 6, c = lin & 63;
        float4 v4 = *(const float4*)&Qb[(size_t)(q0 + r) * HDIM + c];
        QsT[(c + 0) * TPAD + r] = v4.x * 0.125f;
        QsT[(c + 1) * TPAD + r] = v4.y * 0.125f;
        QsT[(c + 2) * TPAD + r] = v4.z * 0.125f;
        QsT[(c + 3) * TPAD + r] = v4.w * 0.125f;
    }

    float m_i[4], l_i[4], o[4][4];
#pragma unroll
    for (int i = 0; i < 4; ++i) {
        m_i[i] = -INFINITY; l_i[i] = 0.0f;
#pragma unroll
        for (int j = 0; j < 4; ++j) o[i][j] = 0.0f;
    }
    __syncthreads();

    const int ntiles = qt + 1;  // causal
    for (int t = 0; t < ntiles; ++t) {
        const int k0 = t * 64;
        // Load K transposed and V tiles
#pragma unroll
        for (int it = 0; it < 4; ++it) {
            int lin = it * 1024 + tid * 4;
            int r = lin >> 6, c = lin & 63;
            float4 kv = *(const float4*)&Kb[(size_t)(k0 + r) * HDIM + c];
            KsT[(c + 0) * TPAD + r] = kv.x;
            KsT[(c + 1) * TPAD + r] = kv.y;
            KsT[(c + 2) * TPAD + r] = kv.z;
            KsT[(c + 3) * TPAD + r] = kv.w;
            float4 vv = *(const float4*)&Vb[(size_t)(k0 + r) * HDIM + c];
            *(float4*)&Vs[r * 64 + c] = vv;
        }
        __syncthreads();

        // S = Q' K^T  — 2x LDS.128 + 16 FMA per d-step
        float s[4][4];
#pragma unroll
        for (int i = 0; i < 4; ++i)
#pragma unroll
            for (int j = 0; j < 4; ++j) s[i][j] = 0.0f;
#pragma unroll 16
        for (int d = 0; d < 64; ++d) {
            float4 a4 = *(const float4*)&QsT[d * TPAD + ty * 4];
            float4 b4 = *(const float4*)&KsT[d * TPAD + tx * 4];
            const float a[4] = { a4.x, a4.y, a4.z, a4.w };
            const float b[4] = { b4.x, b4.y, b4.z, b4.w };
#pragma unroll
            for (int i = 0; i < 4; ++i)
#pragma unroll
                for (int j = 0; j < 4; ++j)
                    s[i][j] = fmaf(a[i], b[j], s[i][j]);
        }

        if (t == qt) {  // diagonal tile: causal mask
#pragma unroll
            for (int i = 0; i < 4; ++i) {
                const int q = q0 + ty * 4 + i;
#pragma unroll
                for (int j = 0; j < 4; ++j)
                    if (k0 + tx * 4 + j > q) s[i][j] = -1e30f;
            }
        }

        // Online softmax
        float p[4][4];
#pragma unroll
        for (int i = 0; i < 4; ++i) {
            float rm = s[i][0];
#pragma unroll
            for (int j = 1; j < 4; ++j) rm = fmaxf(rm, s[i][j]);
#pragma unroll
            for (int off = 1; off < 16; off <<= 1)
                rm = fmaxf(rm, __shfl_xor_sync(0xFFFFFFFFu, rm, off));
            const float mnew = fmaxf(m_i[i], rm);
            float rs = 0.0f;
#pragma unroll
            for (int j = 0; j < 4; ++j) {
                p[i][j] = __expf(s[i][j] - mnew);
                rs += p[i][j];
            }
#pragma unroll
            for (int off = 1; off < 16; off <<= 1)
                rs += __shfl_xor_sync(0xFFFFFFFFu, rs, off);
            const float corr = __expf(m_i[i] - mnew);
            l_i[i] = l_i[i] * corr + rs;
            m_i[i] = mnew;
#pragma unroll
            for (int j = 0; j < 4; ++j) o[i][j] *= corr;
        }

        // Stage P to shared for the PV GEMM
#pragma unroll
        for (int i = 0; i < 4; ++i)
#pragma unroll
            for (int j = 0; j < 4; ++j)
                Ps[(ty * 4 + i) * 64 + tx * 4 + j] = p[i][j];
        __syncthreads();

        // O += P V  (Vs row reads are contiguous & 16B-aligned -> float4)
#pragma unroll 16
        for (int kk = 0; kk < 64; ++kk) {
            float a[4];
            float4 b4 = *(const float4*)&Vs[kk * 64 + tx * 4];
            const float b[4] = { b4.x, b4.y, b4.z, b4.w };
#pragma unroll
            for (int i = 0; i < 4; ++i) a[i] = Ps[(ty * 4 + i) * 64 + kk];
#pragma unroll
            for (int i = 0; i < 4; ++i)
#pragma unroll
                for (int j = 0; j < 4; ++j)
                    o[i][j] = fmaf(a[i], b[j], o[i][j]);
        }
        __syncthreads();
    }

    // Epilogue: normalize and write attn output as [B,S,D]
    const int bb = bh / NHEAD;
    const int h  = bh % NHEAD;
#pragma unroll
    for (int i = 0; i < 4; ++i) {
        const float inv = 1.0f / l_i[i];
        const int q = q0 + ty * 4 + i;
        float* row = O + ((size_t)bb * SEQ + q) * DMODEL + h * HDIM;
#pragma unroll
        for (int j = 0; j < 4; ++j)
            row[tx * 4 + j] = o[i][j] * inv;
    }
}

// ---------------------------------------------------------------------------

extern "C" void kernel_launch(void* const* d_in, const int* in_sizes, int n_in,
                              void* d_out, int out_size)
{
    (void)in_sizes; (void)n_in; (void)out_size;
    const float* x    = (const float*)d_in[0];
    const float* Wq   = (const float*)d_in[1];
    const float* bq   = (const float*)d_in[2];
    const float* Wk   = (const float*)d_in[3];
    const float* bk   = (const float*)d_in[4];
    const float* Wv   = (const float*)d_in[5];
    const float* bv   = (const float*)d_in[6];
    const float* Wo   = (const float*)d_in[7];
    const float* bo   = (const float*)d_in[8];
    const float* comp = (const float*)d_in[9];
    float* out = (float*)d_out;

    float *q, *k, *v, *att;
    cudaGetSymbolAddress((void**)&q,   g_q);
    cudaGetSymbolAddress((void**)&k,   g_k);
    cudaGetSymbolAddress((void**)&v,   g_v);
    cudaGetSymbolAddress((void**)&att, g_att);

    // Fused QKV: one launch, z selects projection. 1536 CTAs fill the chip.
    gemm_qkv<<<dim3(GN / 128, GM / 128, 3), 256>>>(
        x, Wq, bq, q, Wk, bk, k, Wv, bv, v);

    const int smem_bytes = (2 * 64 * TPAD + 2 * 64 * 64) * (int)sizeof(float); // 67584
    cudaFuncSetAttribute(attn_kernel,
                         cudaFuncAttributeMaxDynamicSharedMemorySize, smem_bytes);
    attn_kernel<<<dim3(SEQ / 64, BATCH * NHEAD), 256, smem_bytes>>>(q, k, v, att);

    gemm_out<<<dim3(GN / 128, GM / 128), 256>>>(att, Wo, bo, comp, out);
}

// round 17
// speedup vs baseline: 1.1200x; 1.0152x over previous
#include <cuda_runtime.h>
#include <math.h>

#define BATCH 4
#define SEQ   2048
#define DMODEL 1024
#define NHEAD 16
#define HDIM  64

#define GM (BATCH*SEQ)   // 8192
#define GN DMODEL        // 1024
#define GK DMODEL        // 1024

// Scratch: q,k,v in [B,H,S,HD]; attn output in [B,S,D]
__device__ float g_q[BATCH*NHEAD*SEQ*HDIM];
__device__ float g_k[BATCH*NHEAD*SEQ*HDIM];
__device__ float g_v[BATCH*NHEAD*SEQ*HDIM];
__device__ float g_att[BATCH*SEQ*DMODEL];

// ---------------------------------------------------------------------------
// Packed fp32x2 helpers (sm_100+ PTX f32x2 family -> SASS FFMA2).
// Two independent IEEE fp32 FMAs per instruction: bit-identical numerics.
// ---------------------------------------------------------------------------
__device__ __forceinline__ unsigned long long pack2(float lo, float hi) {
    unsigned long long r;
    asm("mov.b64 %0, {%1, %2};" : "=l"(r) : "f"(lo), "f"(hi));
    return r;
}
__device__ __forceinline__ void unpack2(unsigned long long v, float& lo, float& hi) {
    asm("mov.b64 {%0, %1}, %2;" : "=f"(lo), "=f"(hi) : "l"(v));
}
__device__ __forceinline__ void ffma2(unsigned long long& d,
                                      unsigned long long a, unsigned long long b) {
    asm("fma.rn.f32x2 %0, %1, %2, %0;" : "+l"(d) : "l"(a), "l"(b));
}

// ---------------------------------------------------------------------------
// Double-buffered GEMM mainloop shared by both kernels.
// C[m,n] = sum_k X[m,k]*W[n,k]; 128x128 tile, BK=8, 256 threads, 8x8/thread.
// Smem k-major (transposed on store, padded). Inner loop: 4x LDS.128 +
// 8 splat MOVs + 32 FFMA2 per k-step (vs 64 scalar FFMA before).
// Accumulators stay packed (j-pairs) across the whole mainloop.
// 2-stage pipeline: prefetch next slab to regs during compute, 1 bar/iter.
// ---------------------------------------------------------------------------
__device__ __forceinline__ void gemm_mainloop(
    const float* __restrict__ Xp, const float* __restrict__ Wp,
    float (*As)[8][132], float (*Bs)[8][132],
    int ty, int tx, int lr, int lc, unsigned long long acc2[8][4])
{
    // Preload slab 0 into buffer 0
    {
        const float4 a4 = *(const float4*)(Xp);
        const float4 b4 = *(const float4*)(Wp);
        As[0][lc + 0][lr] = a4.x; As[0][lc + 1][lr] = a4.y;
        As[0][lc + 2][lr] = a4.z; As[0][lc + 3][lr] = a4.w;
        Bs[0][lc + 0][lr] = b4.x; Bs[0][lc + 1][lr] = b4.y;
        Bs[0][lc + 2][lr] = b4.z; Bs[0][lc + 3][lr] = b4.w;
    }
    __syncthreads();

    int s = 0;
    for (int kt = 0; kt < GK; kt += 8) {
        // Prefetch next slab (overlaps with compute below)
        float4 na, nb;
        const bool has_next = (kt + 8 < GK);
        if (has_next) {
            na = *(const float4*)(Xp + kt + 8);
            nb = *(const float4*)(Wp + kt + 8);
        }

        // Compute on buffer s
#pragma unroll
        for (int k = 0; k < 8; ++k) {
            float a[8];
            *(float4*)&a[0] = *(const float4*)&As[s][k][ty * 8];
            *(float4*)&a[4] = *(const float4*)&As[s][k][ty * 8 + 4];
            // b pairs come pre-packed from 16B-aligned smem reads
            const ulonglong2 t0 = *(const ulonglong2*)&Bs[s][k][tx * 8];
            const ulonglong2 t1 = *(const ulonglong2*)&Bs[s][k][tx * 8 + 4];
            unsigned long long b2[4];
            b2[0] = t0.x; b2[1] = t0.y; b2[2] = t1.x; b2[3] = t1.y;
#pragma unroll
            for (int i = 0; i < 8; ++i) {
                const unsigned long long a2 = pack2(a[i], a[i]);
                ffma2(acc2[i][0], a2, b2[0]);
                ffma2(acc2[i][1], a2, b2[1]);
                ffma2(acc2[i][2], a2, b2[2]);
                ffma2(acc2[i][3], a2, b2[3]);
            }
        }

        // Stage next slab into the alternate buffer (safe: its last readers
        // finished before the barrier that ended the previous iteration)
        if (has_next) {
            const int ns = s ^ 1;
            As[ns][lc + 0][lr] = na.x; As[ns][lc + 1][lr] = na.y;
            As[ns][lc + 2][lr] = na.z; As[ns][lc + 3][lr] = na.w;
            Bs[ns][lc + 0][lr] = nb.x; Bs[ns][lc + 1][lr] = nb.y;
            Bs[ns][lc + 2][lr] = nb.z; Bs[ns][lc + 3][lr] = nb.w;
        }
        __syncthreads();
        s ^= 1;
    }
}

// ---------------------------------------------------------------------------
// Fused QKV GEMM: one launch, gridDim.z = 3 selects (Wq,bq,q)/(Wk,bk,k)/(Wv,bv,v).
// Stores permuted into [B,H,S,HD].
// ---------------------------------------------------------------------------
__global__ __launch_bounds__(256, 2) void gemm_qkv(
    const float* __restrict__ X,
    const float* __restrict__ Wq, const float* __restrict__ bq, float* __restrict__ oq,
    const float* __restrict__ Wk, const float* __restrict__ bk, float* __restrict__ ok,
    const float* __restrict__ Wv, const float* __restrict__ bv, float* __restrict__ ov)
{
    const float* W; const float* b1; float* out;
    if (blockIdx.z == 0)      { W = Wq; b1 = bq; out = oq; }
    else if (blockIdx.z == 1) { W = Wk; b1 = bk; out = ok; }
    else                      { W = Wv; b1 = bv; out = ov; }

    __shared__ __align__(16) float As[2][8][132];
    __shared__ __align__(16) float Bs[2][8][132];

    const int n0 = blockIdx.x * 128;
    const int m0 = blockIdx.y * 128;
    const int tid = threadIdx.x;
    const int ty = tid >> 4;
    const int tx = tid & 15;
    const int lr = tid >> 1;
    const int lc = (tid & 1) * 4;

    unsigned long long acc2[8][4];
#pragma unroll
    for (int i = 0; i < 8; ++i)
#pragma unroll
        for (int jp = 0; jp < 4; ++jp) acc2[i][jp] = 0ULL;

    gemm_mainloop(X + (size_t)(m0 + lr) * GK + lc,
                  W + (size_t)(n0 + lr) * GK + lc,
                  As, Bs, ty, tx, lr, lc, acc2);

#pragma unroll
    for (int i = 0; i < 8; ++i) {
        const int m = m0 + ty * 8 + i;
        const int bb = m >> 11;        // /SEQ
        const int ss = m & (SEQ - 1);
        float acc[8];
#pragma unroll
        for (int jp = 0; jp < 4; ++jp)
            unpack2(acc2[i][jp], acc[2 * jp], acc[2 * jp + 1]);
#pragma unroll
        for (int j = 0; j < 8; ++j) {
            const int n = n0 + tx * 8 + j;
            const int h  = n >> 6;         // /HDIM
            const int d  = n & (HDIM - 1);
            out[(((size_t)bb * NHEAD + h) * SEQ + ss) * HDIM + d] = acc[j] + b1[n];
        }
    }
}

// ---------------------------------------------------------------------------
// Output projection GEMM: row-major [M,N] out, adds bias + comp.
// ---------------------------------------------------------------------------
__global__ __launch_bounds__(256, 2) void gemm_out(
    const float* __restrict__ X, const float* __restrict__ W,
    const float* __restrict__ b1, const float* __restrict__ b2,
    float* __restrict__ out)
{
    __shared__ __align__(16) float As[2][8][132];
    __shared__ __align__(16) float Bs[2][8][132];

    const int n0 = blockIdx.x * 128;
    const int m0 = blockIdx.y * 128;
    const int tid = threadIdx.x;
    const int ty = tid >> 4;
    const int tx = tid & 15;
    const int lr = tid >> 1;
    const int lc = (tid & 1) * 4;

    unsigned long long acc2[8][4];
#pragma unroll
    for (int i = 0; i < 8; ++i)
#pragma unroll
        for (int jp = 0; jp < 4; ++jp) acc2[i][jp] = 0ULL;

    gemm_mainloop(X + (size_t)(m0 + lr) * GK + lc,
                  W + (size_t)(n0 + lr) * GK + lc,
                  As, Bs, ty, tx, lr, lc, acc2);

#pragma unroll
    for (int i = 0; i < 8; ++i) {
        const int m = m0 + ty * 8 + i;
        float acc[8];
#pragma unroll
        for (int jp = 0; jp < 4; ++jp)
            unpack2(acc2[i][jp], acc[2 * jp], acc[2 * jp + 1]);
#pragma unroll
        for (int j = 0; j < 8; ++j) {
            const int n = n0 + tx * 8 + j;
            out[(size_t)m * GN + n] = acc[j] + b1[n] + b2[n];
        }
    }
}

// ---------------------------------------------------------------------------
// Flash attention, fp32, causal. One CTA = (bh, 64-row q-tile).
// Q and K tiles stored d-major (QsT[d][row], KsT[d][col], pad 68) so the
// QK^T inner loop is 2x LDS.128 + 4 packs + 8 FFMA2 per d-step.
// LPT scheduling: qt reversed vs blockIdx.x so longest (most K-tiles) CTAs
// launch first, packing the causal-imbalance tail with short CTAs.
// Dynamic shared: QsT(64x68) KsT(64x68) Vs(64x64) Ps(64x64) = 67584 B.
// ---------------------------------------------------------------------------
#define TPAD 68

__global__ __launch_bounds__(256) void attn_kernel(
    const float* __restrict__ Q, const float* __restrict__ K,
    const float* __restrict__ V, float* __restrict__ O)
{
    extern __shared__ float sm[];
    float* QsT = sm;                  // 64*68, QsT[d][r]
    float* KsT = QsT + 64 * TPAD;     // 64*68, KsT[d][c]
    float* Vs  = KsT + 64 * TPAD;     // 64*64, Vs[r][d]
    float* Ps  = Vs + 64 * 64;        // 64*64

    const int qt = gridDim.x - 1 - blockIdx.x;  // longest-first (LPT)
    const int bh = blockIdx.y;
    const int q0 = qt * 64;
    const int tid = threadIdx.x;
    const int ty = tid >> 4;
    const int tx = tid & 15;

    const float* Qb = Q + (size_t)bh * SEQ * HDIM;
    const float* Kb = K + (size_t)bh * SEQ * HDIM;
    const float* Vb = V + (size_t)bh * SEQ * HDIM;

    // Load Q tile transposed, pre-scaled by 1/sqrt(HD)=0.125
#pragma unroll
    for (int it = 0; it < 4; ++it) {
        int lin = it * 1024 + tid * 4;
        int r = lin >> 6, c = lin & 63;
        float4 v4 = *(const float4*)&Qb[(size_t)(q0 + r) * HDIM + c];
        QsT[(c + 0) * TPAD + r] = v4.x * 0.125f;
        QsT[(c + 1) * TPAD + r] = v4.y * 0.125f;
        QsT[(c + 2) * TPAD + r] = v4.z * 0.125f;
        QsT[(c + 3) * TPAD + r] = v4.w * 0.125f;
    }

    float m_i[4], l_i[4], o[4][4];
#pragma unroll
    for (int i = 0; i < 4; ++i) {
        m_i[i] = -INFINITY; l_i[i] = 0.0f;
#pragma unroll
        for (int j = 0; j < 4; ++j) o[i][j] = 0.0f;
    }
    __syncthreads();

    const int ntiles = qt + 1;  // causal
    for (int t = 0; t < ntiles; ++t) {
        const int k0 = t * 64;
        // Load K transposed and V tiles
#pragma unroll
        for (int it = 0; it < 4; ++it) {
            int lin = it * 1024 + tid * 4;
            int r = lin >> 6, c = lin & 63;
            float4 kv = *(const float4*)&Kb[(size_t)(k0 + r) * HDIM + c];
            KsT[(c + 0) * TPAD + r] = kv.x;
            KsT[(c + 1) * TPAD + r] = kv.y;
            KsT[(c + 2) * TPAD + r] = kv.z;
            KsT[(c + 3) * TPAD + r] = kv.w;
            float4 vv = *(const float4*)&Vb[(size_t)(k0 + r) * HDIM + c];
            *(float4*)&Vs[r * 64 + c] = vv;
        }
        __syncthreads();

        // S = Q' K^T — packed fp32x2: 2x LDS.128 + 4 packs + 8 FFMA2 / d-step
        unsigned long long s2[4][2];
#pragma unroll
        for (int i = 0; i < 4; ++i) { s2[i][0] = 0ULL; s2[i][1] = 0ULL; }
#pragma unroll 16
        for (int d = 0; d < 64; ++d) {
            float4 a4 = *(const float4*)&QsT[d * TPAD + ty * 4];
            const ulonglong2 bb2 = *(const ulonglong2*)&KsT[d * TPAD + tx * 4];
            const float a[4] = { a4.x, a4.y, a4.z, a4.w };
#pragma unroll
            for (int i = 0; i < 4; ++i) {
                const unsigned long long a2 = pack2(a[i], a[i]);
                ffma2(s2[i][0], a2, bb2.x);
                ffma2(s2[i][1], a2, bb2.y);
            }
        }
        float s[4][4];
#pragma unroll
        for (int i = 0; i < 4; ++i) {
            unpack2(s2[i][0], s[i][0], s[i][1]);
            unpack2(s2[i][1], s[i][2], s[i][3]);
        }

        if (t == qt) {  // diagonal tile: causal mask
#pragma unroll
            for (int i = 0; i < 4; ++i) {
                const int q = q0 + ty * 4 + i;
#pragma unroll
                for (int j = 0; j < 4; ++j)
                    if (k0 + tx * 4 + j > q) s[i][j] = -1e30f;
            }
        }

        // Online softmax
        float p[4][4];
#pragma unroll
        for (int i = 0; i < 4; ++i) {
            float rm = s[i][0];
#pragma unroll
            for (int j = 1; j < 4; ++j) rm = fmaxf(rm, s[i][j]);
#pragma unroll
            for (int off = 1; off < 16; off <<= 1)
                rm = fmaxf(rm, __shfl_xor_sync(0xFFFFFFFFu, rm, off));
            const float mnew = fmaxf(m_i[i], rm);
            float rs = 0.0f;
#pragma unroll
            for (int j = 0; j < 4; ++j) {
                p[i][j] = __expf(s[i][j] - mnew);
                rs += p[i][j];
            }
#pragma unroll
            for (int off = 1; off < 16; off <<= 1)
                rs += __shfl_xor_sync(0xFFFFFFFFu, rs, off);
            const float corr = __expf(m_i[i] - mnew);
            l_i[i] = l_i[i] * corr + rs;
            m_i[i] = mnew;
#pragma unroll
            for (int j = 0; j < 4; ++j) o[i][j] *= corr;
        }

        // Stage P to shared for the PV GEMM
#pragma unroll
        for (int i = 0; i < 4; ++i)
#pragma unroll
            for (int j = 0; j < 4; ++j)
                Ps[(ty * 4 + i) * 64 + tx * 4 + j] = p[i][j];
        __syncthreads();

        // O += P V  (Vs row reads are contiguous & 16B-aligned -> float4)
#pragma unroll 16
        for (int kk = 0; kk < 64; ++kk) {
            float a[4];
            float4 b4 = *(const float4*)&Vs[kk * 64 + tx * 4];
            const float b[4] = { b4.x, b4.y, b4.z, b4.w };
#pragma unroll
            for (int i = 0; i < 4; ++i) a[i] = Ps[(ty * 4 + i) * 64 + kk];
#pragma unroll
            for (int i = 0; i < 4; ++i)
#pragma unroll
                for (int j = 0; j < 4; ++j)
                    o[i][j] = fmaf(a[i], b[j], o[i][j]);
        }
        __syncthreads();
    }

    // Epilogue: normalize and write attn output as [B,S,D]
    const int bb = bh / NHEAD;
    const int h  = bh % NHEAD;
#pragma unroll
    for (int i = 0; i < 4; ++i) {
        const float inv = 1.0f / l_i[i];
        const int q = q0 + ty * 4 + i;
        float* row = O + ((size_t)bb * SEQ + q) * DMODEL + h * HDIM;
#pragma unroll
        for (int j = 0; j < 4; ++j)
            row[tx * 4 + j] = o[i][j] * inv;
    }
}

// ---------------------------------------------------------------------------

extern "C" void kernel_launch(void* const* d_in, const int* in_sizes, int n_in,
                              void* d_out, int out_size)
{
    (void)in_sizes; (void)n_in; (void)out_size;
    const float* x    = (const float*)d_in[0];
    const float* Wq   = (const float*)d_in[1];
    const float* bq   = (const float*)d_in[2];
    const float* Wk   = (const float*)d_in[3];
    const float* bk   = (const float*)d_in[4];
    const float* Wv   = (const float*)d_in[5];
    const float* bv   = (const float*)d_in[6];
    const float* Wo   = (const float*)d_in[7];
    const float* bo   = (const float*)d_in[8];
    const float* comp = (const float*)d_in[9];
    float* out = (float*)d_out;

    float *q, *k, *v, *att;
    cudaGetSymbolAddress((void**)&q,   g_q);
    cudaGetSymbolAddress((void**)&k,   g_k);
    cudaGetSymbolAddress((void**)&v,   g_v);
    cudaGetSymbolAddress((void**)&att, g_att);

    // Fused QKV: one launch, z selects projection. 1536 CTAs fill the chip.
    gemm_qkv<<<dim3(GN / 128, GM / 128, 3), 256>>>(
        x, Wq, bq, q, Wk, bk, k, Wv, bv, v);

    const int smem_bytes = (2 * 64 * TPAD + 2 * 64 * 64) * (int)sizeof(float); // 67584
    cudaFuncSetAttribute(attn_kernel,
                         cudaFuncAttributeMaxDynamicSharedMemorySize, smem_bytes);
    attn_kernel<<<dim3(SEQ / 64, BATCH * NHEAD), 256, smem_bytes>>>(q, k, v, att);

    gemm_out<<<dim3(GN / 128, GM / 128), 256>>>(att, Wo, bo, comp, out);
}